// round 3
// baseline (speedup 1.0000x reference)
#include <cuda_runtime.h>
#include <cuda_bf16.h>

// Encoder_57380763074770: batched GRU cell.
// Inputs (metadata order):
//  0: x        [64,17]  f32
//  1: ip       [64,8]   i32
//  2: port     [64,2]   i32
//  3: hidden   [1,1,128] f32
//  4: ip_emb   [256,1]  f32
//  5: port_emb [70000,4] f32
//  6: W_ih     [384,33] f32
//  7: W_hh     [384,128] f32
//  8: b_ih     [384]    f32
//  9: b_hh     [384]    f32
// Output: outputs [64,128] f32 (+ new_hidden [128] appended if room)

#define H 128
#define FIN 33
#define STEPS 64
#define WIH_ELEMS (3 * H * FIN)   // 12672

__global__ void __launch_bounds__(128, 1)
encoder_kernel(const float* __restrict__ x,
               const int*   __restrict__ ip,
               const int*   __restrict__ port,
               const float* __restrict__ hidden,
               const float* __restrict__ ip_emb,
               const float* __restrict__ port_emb,
               const float* __restrict__ W_ih,
               const float* __restrict__ W_hh,
               const float* __restrict__ b_ih,
               const float* __restrict__ b_hh,
               float* __restrict__ out,
               int out_size)
{
    extern __shared__ float sm[];
    float* sW   = sm;                  // 12672 floats: W_ih staged
    float* s_xi = sm + WIH_ELEMS;      // 36 (33 used)
    float* s_h0 = s_xi + 36;           // 128
    float* s_gh = s_h0 + H;            // 384

    const int s    = blockIdx.x;       // step 0..63
    const int t    = threadIdx.x;      // 0..127
    const int lane = t & 31;
    const int warp = t >> 5;

    // ---- assemble xi[33] = concat(x[s], ip_emb[ip[s]], port_emb[port[s]]) ----
    if (t < 17) {
        s_xi[t] = x[s * 17 + t];
    } else if (t < 25) {
        s_xi[t] = ip_emb[ip[s * 8 + (t - 17)]];   // ip_emb dim=1
    } else if (t < 33) {
        int q = t - 25;
        s_xi[t] = port_emb[port[s * 2 + (q >> 2)] * 4 + (q & 3)];
    }
    // h0
    s_h0[t] = hidden[t];
    __syncthreads();

    // ---- stage W_ih into shared (coalesced float4) ----
    {
        const float4* src = reinterpret_cast<const float4*>(W_ih);
        float4* dst = reinterpret_cast<float4*>(sW);
        #pragma unroll
        for (int i = t; i < WIH_ELEMS / 4; i += 128)
            dst[i] = src[i];
    }

    // ---- gh[j] = h0 . W_hh[j] + b_hh[j], coalesced warp-reduce (96 rows/warp) ----
    for (int j = warp; j < 3 * H; j += 4) {
        const float* row = W_hh + j * H;
        float p = s_h0[lane]        * row[lane]
                + s_h0[lane + 32]   * row[lane + 32]
                + s_h0[lane + 64]   * row[lane + 64]
                + s_h0[lane + 96]   * row[lane + 96];
        #pragma unroll
        for (int off = 16; off > 0; off >>= 1)
            p += __shfl_down_sync(0xffffffffu, p, off);
        if (lane == 0) s_gh[j] = p + b_hh[j];
    }
    __syncthreads();

    // ---- gi rows j, j+128, j+256 (shared reads: stride 33 -> conflict-free) ----
    const float* w0 = sW + t * FIN;
    const float* w1 = sW + (t + H) * FIN;
    const float* w2 = sW + (t + 2 * H) * FIN;
    float a0 = b_ih[t], a1 = b_ih[t + H], a2 = b_ih[t + 2 * H];
    #pragma unroll
    for (int k = 0; k < FIN; k++) {
        const float xv = s_xi[k];
        a0 = fmaf(xv, w0[k], a0);
        a1 = fmaf(xv, w1[k], a1);
        a2 = fmaf(xv, w2[k], a2);
    }

    // ---- gates ----
    const float r = 1.0f / (1.0f + __expf(-(a0 + s_gh[t])));
    const float z = 1.0f / (1.0f + __expf(-(a1 + s_gh[t + H])));
    const float n = tanhf(a2 + r * s_gh[t + 2 * H]);
    const float h0v = s_h0[t];
    const float o = (1.0f - z) * n + z * h0v;

    out[s * H + t] = o;
    if (s == STEPS - 1 && out_size >= STEPS * H + H)
        out[STEPS * H + t] = o;   // new_hidden = outputs[last]
}

extern "C" void kernel_launch(void* const* d_in, const int* in_sizes, int n_in,
                              void* d_out, int out_size)
{
    const float* x        = (const float*)d_in[0];
    const int*   ip       = (const int*)  d_in[1];
    const int*   port     = (const int*)  d_in[2];
    const float* hidden   = (const float*)d_in[3];
    const float* ip_emb   = (const float*)d_in[4];
    const float* port_emb = (const float*)d_in[5];
    const float* W_ih     = (const float*)d_in[6];
    const float* W_hh     = (const float*)d_in[7];
    const float* b_ih     = (const float*)d_in[8];
    const float* b_hh     = (const float*)d_in[9];

    const int smem = (WIH_ELEMS + 36 + H + 3 * H) * (int)sizeof(float); // ~53 KB
    static bool attr_set = false;
    if (!attr_set) {
        cudaFuncSetAttribute(encoder_kernel,
                             cudaFuncAttributeMaxDynamicSharedMemorySize, smem);
        attr_set = true;
    }

    encoder_kernel<<<STEPS, 128, smem>>>(x, ip, port, hidden, ip_emb, port_emb,
                                         W_ih, W_hh, b_ih, b_hh,
                                         (float*)d_out, out_size);
}

// round 5
// speedup vs baseline: 3.1176x; 3.1176x over previous
#include <cuda_runtime.h>
#include <cuda_bf16.h>

// Encoder_57380763074770: batched GRU cell.
// Inputs (metadata order):
//  0: x        [64,17]  f32
//  1: ip       [64,8]   i32
//  2: port     [64,2]   i32
//  3: hidden   [1,1,128] f32
//  4: ip_emb   [256,1]  f32
//  5: port_emb [70000,4] f32
//  6: W_ih     [384,33] f32
//  7: W_hh     [384,128] f32
//  8: b_ih     [384]    f32
//  9: b_hh     [384]    f32
// Output 0: outputs [64,128] f32
// Output 1: new_hidden [1,1,128] f32 = outputs[63], appended at offset 64*128

#define H 128
#define FIN 33
#define STEPS 64
#define WIH_ELEMS (3 * H * FIN)   // 12672

// gh[384] = h0 @ W_hh^T + b_hh  — step-independent, computed once.
__device__ float g_gh[3 * H];

// K1: one warp per gh row. 96 blocks x 128 threads = 384 warps.
__global__ void __launch_bounds__(128, 1)
gh_kernel(const float* __restrict__ hidden,
          const float* __restrict__ W_hh,
          const float* __restrict__ b_hh)
{
    const int lane = threadIdx.x & 31;
    const int j    = blockIdx.x * 4 + (threadIdx.x >> 5);  // row 0..383

    // coalesced float4 reads: warp covers the whole 128-float row / h0
    const float4 hv = reinterpret_cast<const float4*>(hidden)[lane];
    const float4 wv = reinterpret_cast<const float4*>(W_hh + j * H)[lane];

    float p = hv.x * wv.x + hv.y * wv.y + hv.z * wv.z + hv.w * wv.w;
    #pragma unroll
    for (int off = 16; off > 0; off >>= 1)
        p += __shfl_down_sync(0xffffffffu, p, off);

    if (lane == 0) g_gh[j] = p + b_hh[j];
}

// K2: one block per step, one thread per hidden unit.
__global__ void __launch_bounds__(128, 1)
step_kernel(const float* __restrict__ x,
            const int*   __restrict__ ip,
            const int*   __restrict__ port,
            const float* __restrict__ hidden,
            const float* __restrict__ ip_emb,
            const float* __restrict__ port_emb,
            const float* __restrict__ W_ih,
            const float* __restrict__ b_ih,
            float* __restrict__ out,
            int out_size)
{
    extern __shared__ float sm[];
    float* sW   = sm;                 // 12672 floats: W_ih staged
    float* s_xi = sm + WIH_ELEMS;     // 36 (33 used)

    const int s = blockIdx.x;         // step 0..63
    const int t = threadIdx.x;        // 0..127

    // --- issue all step-independent global loads up front (coalesced, L2) ---
    const float gh_r = g_gh[t];
    const float gh_z = g_gh[t + H];
    const float gh_n = g_gh[t + 2 * H];
    const float h0v  = hidden[t];
    float a0 = b_ih[t], a1 = b_ih[t + H], a2 = b_ih[t + 2 * H];

    // --- assemble xi[33] = concat(x[s], ip_emb[ip[s]], port_emb[port[s]]) ---
    if (t < 17) {
        s_xi[t] = x[s * 17 + t];
    } else if (t < 25) {
        s_xi[t] = ip_emb[ip[s * 8 + (t - 17)]];          // ip_emb dim=1
    } else if (t < 33) {
        int q = t - 25;
        s_xi[t] = port_emb[port[s * 2 + (q >> 2)] * 4 + (q & 3)];
    }

    // --- stage W_ih into shared (coalesced float4) ---
    {
        const float4* src = reinterpret_cast<const float4*>(W_ih);
        float4* dst = reinterpret_cast<float4*>(sW);
        #pragma unroll
        for (int i = t; i < WIH_ELEMS / 4; i += 128)
            dst[i] = src[i];
    }
    __syncthreads();

    // --- gi rows t, t+128, t+256 (shared reads: stride 33 -> conflict-free) ---
    const float* w0 = sW + t * FIN;
    const float* w1 = sW + (t + H) * FIN;
    const float* w2 = sW + (t + 2 * H) * FIN;
    #pragma unroll
    for (int k = 0; k < FIN; k++) {
        const float xv = s_xi[k];
        a0 = fmaf(xv, w0[k], a0);
        a1 = fmaf(xv, w1[k], a1);
        a2 = fmaf(xv, w2[k], a2);
    }

    // --- gates ---
    const float r = 1.0f / (1.0f + __expf(-(a0 + gh_r)));
    const float z = 1.0f / (1.0f + __expf(-(a1 + gh_z)));
    const float n = tanhf(a2 + r * gh_n);
    const float o = (1.0f - z) * n + z * h0v;

    out[s * H + t] = o;
    // Output 1: new_hidden = outputs[last step]
    if (s == STEPS - 1 && out_size >= STEPS * H + H)
        out[STEPS * H + t] = o;
}

extern "C" void kernel_launch(void* const* d_in, const int* in_sizes, int n_in,
                              void* d_out, int out_size)
{
    const float* x        = (const float*)d_in[0];
    const int*   ip       = (const int*)  d_in[1];
    const int*   port     = (const int*)  d_in[2];
    const float* hidden   = (const float*)d_in[3];
    const float* ip_emb   = (const float*)d_in[4];
    const float* port_emb = (const float*)d_in[5];
    const float* W_ih     = (const float*)d_in[6];
    const float* W_hh     = (const float*)d_in[7];
    const float* b_ih     = (const float*)d_in[8];
    const float* b_hh     = (const float*)d_in[9];

    const int smem = (WIH_ELEMS + 36) * (int)sizeof(float);  // ~50.8 KB
    static bool attr_set = false;
    if (!attr_set) {
        cudaFuncSetAttribute(step_kernel,
                             cudaFuncAttributeMaxDynamicSharedMemorySize, smem);
        attr_set = true;
    }

    gh_kernel<<<96, 128>>>(hidden, W_hh, b_hh);
    step_kernel<<<STEPS, 128, smem>>>(x, ip, port, hidden, ip_emb, port_emb,
                                      W_ih, b_ih, (float*)d_out, out_size);
}

// round 6
// speedup vs baseline: 3.1292x; 1.0037x over previous
#include <cuda_runtime.h>
#include <cuda_bf16.h>

// Encoder_57380763074770: batched GRU cell.
// Inputs (metadata order):
//  0: x        [64,17]  f32
//  1: ip       [64,8]   i32
//  2: port     [64,2]   i32
//  3: hidden   [1,1,128] f32
//  4: ip_emb   [256,1]  f32
//  5: port_emb [70000,4] f32
//  6: W_ih     [384,33] f32
//  7: W_hh     [384,128] f32
//  8: b_ih     [384]    f32
//  9: b_hh     [384]    f32
// Output 0: outputs [64,128] f32
// Output 1: new_hidden [1,1,128] f32 = outputs[63], at offset 64*128

#define H 128
#define FIN 33
#define STEPS 64

// Scratch (device globals — no allocation allowed in kernel_launch).
__device__ float g_gh[3 * H];            // h0 @ W_hh^T + b_hh   (step-independent)
__device__ float g_gi[STEPS * 3 * H];    // xi @ W_ih^T + b_ih   (per step)

// K1: blocks 0..95   -> gh rows (1 warp per row, 384 rows)
//     blocks 96..287 -> gi: block handles 128 rows of one step
__global__ void __launch_bounds__(128, 1)
prep_kernel(const float* __restrict__ x,
            const int*   __restrict__ ip,
            const int*   __restrict__ port,
            const float* __restrict__ hidden,
            const float* __restrict__ ip_emb,
            const float* __restrict__ port_emb,
            const float* __restrict__ W_ih,
            const float* __restrict__ W_hh,
            const float* __restrict__ b_ih,
            const float* __restrict__ b_hh)
{
    const int t    = threadIdx.x;
    const int lane = t & 31;

    if (blockIdx.x < 96) {
        // ---- gh[j] = h0 . W_hh[j] + b_hh[j] ----
        const int j = blockIdx.x * 4 + (t >> 5);   // row 0..383
        const float4 hv = reinterpret_cast<const float4*>(hidden)[lane];
        const float4 wv = reinterpret_cast<const float4*>(W_hh + j * H)[lane];
        float p = hv.x * wv.x + hv.y * wv.y + hv.z * wv.z + hv.w * wv.w;
        #pragma unroll
        for (int off = 16; off > 0; off >>= 1)
            p += __shfl_down_sync(0xffffffffu, p, off);
        if (lane == 0) g_gh[j] = p + b_hh[j];
        return;
    }

    // ---- gi block: step s, row group rg (rows rg*128 + t) ----
    const int b  = blockIdx.x - 96;     // 0..191
    const int s  = b / 3;               // step 0..63
    const int rg = b % 3;               // row group 0..2
    const int j  = rg * H + t;          // gi row 0..383

    __shared__ float s_xi[36];

    // Front-issue this thread's W_ih row into registers (coalesced across warp:
    // lanes cover 32 contiguous 132-byte rows). Overlaps the xi gather below.
    float w[FIN];
    const float* wr = W_ih + j * FIN;
    #pragma unroll
    for (int k = 0; k < FIN; k++)
        w[k] = wr[k];

    // Assemble xi[33] = concat(x[s], ip_emb[ip[s]], port_emb[port[s]])
    if (t < 17) {
        s_xi[t] = x[s * 17 + t];
    } else if (t < 25) {
        s_xi[t] = ip_emb[ip[s * 8 + (t - 17)]];          // ip_emb dim=1
    } else if (t < 33) {
        int q = t - 25;
        s_xi[t] = port_emb[port[s * 2 + (q >> 2)] * 4 + (q & 3)];
    }
    __syncthreads();

    float a = b_ih[j];
    #pragma unroll
    for (int k = 0; k < FIN; k++)
        a = fmaf(s_xi[k], w[k], a);     // LDS broadcast, conflict-free

    g_gi[s * 3 * H + j] = a;
}

// K2: pure elementwise gates. Block = step, thread = hidden unit.
__global__ void __launch_bounds__(128, 1)
gate_kernel(const float* __restrict__ hidden,
            float* __restrict__ out,
            int out_size)
{
    const int s = blockIdx.x;
    const int t = threadIdx.x;

    const float* gi = g_gi + s * 3 * H;
    const float i_r = gi[t];
    const float i_z = gi[t + H];
    const float i_n = gi[t + 2 * H];
    const float h_r = g_gh[t];
    const float h_z = g_gh[t + H];
    const float h_n = g_gh[t + 2 * H];
    const float h0v = hidden[t];

    const float r = 1.0f / (1.0f + __expf(-(i_r + h_r)));
    const float z = 1.0f / (1.0f + __expf(-(i_z + h_z)));
    const float n = tanhf(i_n + r * h_n);
    const float o = (1.0f - z) * n + z * h0v;

    out[s * H + t] = o;
    if (s == STEPS - 1 && out_size >= STEPS * H + H)
        out[STEPS * H + t] = o;         // Output 1: new_hidden
}

extern "C" void kernel_launch(void* const* d_in, const int* in_sizes, int n_in,
                              void* d_out, int out_size)
{
    const float* x        = (const float*)d_in[0];
    const int*   ip       = (const int*)  d_in[1];
    const int*   port     = (const int*)  d_in[2];
    const float* hidden   = (const float*)d_in[3];
    const float* ip_emb   = (const float*)d_in[4];
    const float* port_emb = (const float*)d_in[5];
    const float* W_ih     = (const float*)d_in[6];
    const float* W_hh     = (const float*)d_in[7];
    const float* b_ih     = (const float*)d_in[8];
    const float* b_hh     = (const float*)d_in[9];

    prep_kernel<<<288, 128>>>(x, ip, port, hidden, ip_emb, port_emb,
                              W_ih, W_hh, b_ih, b_hh);
    gate_kernel<<<STEPS, 128>>>(hidden, (float*)d_out, out_size);
}